// round 6
// baseline (speedup 1.0000x reference)
#include <cuda_runtime.h>
#include <cuda_bf16.h>

#define SEQ   512
#define BATCH 128
#define DIN   512
#define DH    1024
#define DOUT  256
#define WROW  (DIN + DH)   // 1536, W_i2h row length

#define NBLK   128
#define NTHR   256
#define KSPLIT 4

// SMEM layout for persistent kernel (floats)
#define SWH_FLOATS (256 * 64)      // Wh slice [256 k][64 j]
#define SH_STRIDE  260             // padded row for bank-conflict-free h reads
#define SH_FLOATS  (64 * SH_STRIDE)
#define SMEM_BYTES ((SWH_FLOATS + SH_FLOATS) * 4)   // 132096 B

// Device-global scratch (allocation-free rule: __device__ arrays)
__device__ float    g_xW[SEQ * BATCH * DH];      // 256 MB: precomputed input projections
__device__ float    g_H[BATCH * DH];             // current hidden state
__device__ float    g_Cpart[KSPLIT * BATCH * DH];// split-K partials
__device__ unsigned g_bar_count;
__device__ unsigned g_bar_flag;

// ---------------------------------------------------------------------------
// Init: copy initial hidden state, reset barrier (fresh state every launch ->
// deterministic, graph-replay safe)
// ---------------------------------------------------------------------------
__global__ void k_init(const float* __restrict__ hidden)
{
    int i = blockIdx.x * blockDim.x + threadIdx.x;
    if (i < BATCH * DH) g_H[i] = hidden[i];
    if (i == 0) { g_bar_count = 0; g_bar_flag = 0; }
}

// ---------------------------------------------------------------------------
// Precompute xW[s,b,:] = x[s,b,:] @ Wx   (M=65536, N=1024, K=512)
// fp32 SGEMM: 128x128 block tile, 8x8 microtile, BK=8, double-buffered SMEM.
// ---------------------------------------------------------------------------
__global__ void __launch_bounds__(256, 2) k_xw(
    const float* __restrict__ A,     // x, [65536][512]
    const float* __restrict__ W)     // W_i2h, [1024][1536]; Wx[k][n] = W[n][k]
{
    __shared__ float sA[2][8][132];
    __shared__ float sB[2][8][132];

    const int tid = threadIdx.x;
    const int m0  = blockIdx.y << 7;
    const int n0  = blockIdx.x << 7;
    const int row = tid >> 1;        // 0..127
    const int q   = tid & 1;         // which float4 of the 8-wide k chunk
    const int tm  = tid & 15;
    const int tn  = tid >> 4;

    const float* Aptr = A + (m0 + row) * DIN  + (q << 2);
    const float* Wptr = W + (n0 + row) * WROW + (q << 2);

    // load tile 0
    {
        float4 a = *(const float4*)Aptr;
        float4 b = *(const float4*)Wptr;
        sA[0][q * 4 + 0][row] = a.x; sA[0][q * 4 + 1][row] = a.y;
        sA[0][q * 4 + 2][row] = a.z; sA[0][q * 4 + 3][row] = a.w;
        sB[0][q * 4 + 0][row] = b.x; sB[0][q * 4 + 1][row] = b.y;
        sB[0][q * 4 + 2][row] = b.z; sB[0][q * 4 + 3][row] = b.w;
    }
    __syncthreads();

    float acc[8][8];
    #pragma unroll
    for (int i = 0; i < 8; ++i)
        #pragma unroll
        for (int j = 0; j < 8; ++j) acc[i][j] = 0.f;

    int buf = 0;
    for (int cb = 0; cb < 64; ++cb) {
        float4 ra, rb;
        const bool more = (cb < 63);
        if (more) {
            ra = *(const float4*)(Aptr + (cb + 1) * 8);
            rb = *(const float4*)(Wptr + (cb + 1) * 8);
        }
        #pragma unroll
        for (int k = 0; k < 8; ++k) {
            float4 a0 = *(const float4*)&sA[buf][k][tm << 2];
            float4 a1 = *(const float4*)&sA[buf][k][64 + (tm << 2)];
            float4 b0 = *(const float4*)&sB[buf][k][tn << 2];
            float4 b1 = *(const float4*)&sB[buf][k][64 + (tn << 2)];
            float am[8] = {a0.x, a0.y, a0.z, a0.w, a1.x, a1.y, a1.z, a1.w};
            float bn[8] = {b0.x, b0.y, b0.z, b0.w, b1.x, b1.y, b1.z, b1.w};
            #pragma unroll
            for (int i = 0; i < 8; ++i)
                #pragma unroll
                for (int j = 0; j < 8; ++j)
                    acc[i][j] += am[i] * bn[j];
        }
        if (more) {
            int nb = buf ^ 1;
            sA[nb][q * 4 + 0][row] = ra.x; sA[nb][q * 4 + 1][row] = ra.y;
            sA[nb][q * 4 + 2][row] = ra.z; sA[nb][q * 4 + 3][row] = ra.w;
            sB[nb][q * 4 + 0][row] = rb.x; sB[nb][q * 4 + 1][row] = rb.y;
            sB[nb][q * 4 + 2][row] = rb.z; sB[nb][q * 4 + 3][row] = rb.w;
            __syncthreads();
            buf = nb;
        }
    }

    #pragma unroll
    for (int i = 0; i < 8; ++i) {
        int m = m0 + ((i < 4) ? ((tm << 2) + i) : (64 + (tm << 2) + (i - 4)));
        float4 v0 = make_float4(acc[i][0], acc[i][1], acc[i][2], acc[i][3]);
        float4 v1 = make_float4(acc[i][4], acc[i][5], acc[i][6], acc[i][7]);
        *(float4*)&g_xW[m * DH + n0 + (tn << 2)]      = v0;
        *(float4*)&g_xW[m * DH + n0 + 64 + (tn << 2)] = v1;
    }
}

// ---------------------------------------------------------------------------
// Grid barrier: generation counter, reset by k_init each launch.
// ---------------------------------------------------------------------------
__device__ __forceinline__ void grid_barrier(unsigned nblk, unsigned& gen)
{
    __threadfence();
    __syncthreads();
    if (threadIdx.x == 0) {
        gen += 1;
        unsigned a = atomicAdd(&g_bar_count, 1u);
        if (a == nblk - 1u) {
            atomicExch(&g_bar_count, 0u);
            __threadfence();
            *(volatile unsigned*)&g_bar_flag = gen;
        } else {
            while (*(volatile unsigned*)&g_bar_flag != gen) { }
        }
    }
    __syncthreads();
}

// ---------------------------------------------------------------------------
// Persistent recurrence kernel. 128 blocks (one per SM, all co-resident).
// Block decode: bx (b-tile of 64) x jx (j-tile of 64) x kx (k-slice of 256).
// Wh slice stays in SMEM for the whole kernel. Two grid barriers per step.
// Epilogue (logits + softmax + h_final copy) fused at the end.
// ---------------------------------------------------------------------------
__global__ void __launch_bounds__(NTHR, 1) k_rnn(
    const float* __restrict__ Wi2h, const float* __restrict__ bi2h,
    const float* __restrict__ Wh2o, const float* __restrict__ bh2o,
    float* __restrict__ out, int out_size)
{
    extern __shared__ float smem[];
    float* sWh = smem;               // [256 k][64 j]
    float* sH  = smem + SWH_FLOATS;  // [64 b][260] (padded)

    const int tid = threadIdx.x;
    const int blk = blockIdx.x;
    const int bx  = blk & 1;
    const int jx  = (blk >> 1) & 15;
    const int kx  = blk >> 5;
    const int b0  = bx << 6;
    const int j0  = jx << 6;
    const int k0  = kx << 8;

    // Load Wh slice (transposed to [k][j]) ONCE. Wh[k][j] = W_i2h[j][DIN+k].
    for (int p = tid; p < 64 * 64; p += NTHR) {
        int j  = p >> 6;
        int kq = p & 63;
        float4 v = *(const float4*)&Wi2h[(j0 + j) * WROW + DIN + k0 + (kq << 2)];
        sWh[(kq * 4 + 0) * 64 + j] = v.x;
        sWh[(kq * 4 + 1) * 64 + j] = v.y;
        sWh[(kq * 4 + 2) * 64 + j] = v.z;
        sWh[(kq * 4 + 3) * 64 + j] = v.w;
    }

    const int tx = tid & 15;   // j quad
    const int ty = tid >> 4;   // b quad
    unsigned gen = 0;
    const int gtid = blk * NTHR + tid;                // 0..32767
    const float4* Cp4 = (const float4*)g_Cpart;
    const float4* xW4 = (const float4*)g_xW;
    float4* H4 = (float4*)g_H;
    const int pj = (gtid << 2) & (DH - 1);
    const float4 bias = *(const float4*)&bi2h[pj];

    const float* wp = sWh + (tx << 2);
    const float* hp = sH + (ty << 2) * SH_STRIDE;

    for (int t = 0; t < SEQ; ++t) {
        // Load H slice [64 b][256 k] into SMEM
        for (int p = tid; p < 64 * 64; p += NTHR) {
            int bl = p >> 6;
            int kq = p & 63;
            float4 v = *(const float4*)&g_H[(b0 + bl) * DH + k0 + (kq << 2)];
            *(float4*)&sH[bl * SH_STRIDE + (kq << 2)] = v;
        }
        __syncthreads();

        // Phase 1: partial GEMM, microtile 4b x 4j over 256 k
        float acc[4][4];
        #pragma unroll
        for (int i = 0; i < 4; ++i)
            #pragma unroll
            for (int j = 0; j < 4; ++j) acc[i][j] = 0.f;

        #pragma unroll 8
        for (int k = 0; k < 256; ++k) {
            float4 w = *(const float4*)(wp + (k << 6));
            float hh[4];
            hh[0] = hp[k];
            hh[1] = hp[k + SH_STRIDE];
            hh[2] = hp[k + 2 * SH_STRIDE];
            hh[3] = hp[k + 3 * SH_STRIDE];
            float ww[4] = {w.x, w.y, w.z, w.w};
            #pragma unroll
            for (int i = 0; i < 4; ++i)
                #pragma unroll
                for (int j = 0; j < 4; ++j)
                    acc[i][j] += hh[i] * ww[j];
        }

        #pragma unroll
        for (int i = 0; i < 4; ++i) {
            float4 v = make_float4(acc[i][0], acc[i][1], acc[i][2], acc[i][3]);
            *(float4*)&g_Cpart[kx * (BATCH * DH) +
                               (b0 + (ty << 2) + i) * DH + j0 + (tx << 2)] = v;
        }

        grid_barrier(gridDim.x, gen);

        // Phase 2: reduce 4 partials + xW + bias, tanh, write H (1 float4/thread)
        {
            float4 c0 = Cp4[gtid];
            float4 c1 = Cp4[32768 + gtid];
            float4 c2 = Cp4[65536 + gtid];
            float4 c3 = Cp4[98304 + gtid];
            float4 xw = xW4[t * 32768 + gtid];
            float4 r;
            r.x = tanhf(c0.x + c1.x + c2.x + c3.x + xw.x + bias.x);
            r.y = tanhf(c0.y + c1.y + c2.y + c3.y + xw.y + bias.y);
            r.z = tanhf(c0.z + c1.z + c2.z + c3.z + xw.z + bias.z);
            r.w = tanhf(c0.w + c1.w + c2.w + c3.w + xw.w + bias.w);
            H4[gtid] = r;
        }

        grid_barrier(gridDim.x, gen);
    }

    // ------------------- Epilogue: logits + softmax -------------------
    // One block per batch row (NBLK == BATCH). Thread = output class.
    {
        float* sv   = smem;          // h row [1024]
        float* sred = smem + 1024;   // reduction [256]
        const int b = blk;

        ((float4*)sv)[tid] = *(const float4*)&g_H[b * DH + (tid << 2)];
        __syncthreads();

        float acc = 0.f;
        const float4* wr = (const float4*)(Wh2o + tid * DH);
        #pragma unroll 8
        for (int qq = 0; qq < DH / 4; ++qq) {
            float4 w = wr[qq];
            float4 h = ((const float4*)sv)[qq];
            acc += w.x * h.x + w.y * h.y + w.z * h.z + w.w * h.w;
        }
        float logit = acc + bh2o[tid];

        sred[tid] = logit;
        __syncthreads();
        for (int s = 128; s > 0; s >>= 1) {
            if (tid < s) sred[tid] = fmaxf(sred[tid], sred[tid + s]);
            __syncthreads();
        }
        float mx = sred[0];
        __syncthreads();
        float e = expf(logit - mx);
        sred[tid] = e;
        __syncthreads();
        for (int s = 128; s > 0; s >>= 1) {
            if (tid < s) sred[tid] += sred[tid + s];
            __syncthreads();
        }
        float inv = 1.f / sred[0];
        out[b * DOUT + tid] = e * inv;
    }

    // h_final (second output tensor), grid-stride copy
    if (out_size >= BATCH * DOUT + BATCH * DH) {
        for (int i = gtid; i < BATCH * DH; i += NBLK * NTHR)
            out[BATCH * DOUT + i] = g_H[i];
    }
}

// ---------------------------------------------------------------------------
extern "C" void kernel_launch(void* const* d_in, const int* in_sizes, int n_in,
                              void* d_out, int out_size)
{
    const float* x      = (const float*)d_in[0];
    const float* hidden = (const float*)d_in[1];
    const float* Wi2h   = (const float*)d_in[2];
    const float* bi2h   = (const float*)d_in[3];
    const float* Wh2o   = (const float*)d_in[4];
    const float* bh2o   = (const float*)d_in[5];
    float* out = (float*)d_out;

    cudaFuncSetAttribute(k_rnn, cudaFuncAttributeMaxDynamicSharedMemorySize,
                         SMEM_BYTES);

    k_init<<<512, 256>>>(hidden);

    dim3 gx(DH / 128, (SEQ * BATCH) / 128);   // (8, 512)
    k_xw<<<gx, 256>>>(x, Wi2h);

    k_rnn<<<NBLK, NTHR, SMEM_BYTES>>>(Wi2h, bi2h, Wh2o, bh2o, out, out_size);
}